// round 10
// baseline (speedup 1.0000x reference)
#include <cuda_runtime.h>
#include <math.h>

#define BATCH 64
#define NTOK  4096
#define NS    8
#define SCALE 0.125f
#define EPSV  1e-8f
#define LN_EPS 1e-5f

__device__ float g_slots[BATCH][NS][64];
__device__ float g_Qk[BATCH][NS][64];
__device__ float g_T[BATCH][NS];
__device__ float g_C[BATCH][NS];
__device__ float g_Z[BATCH][NS][64];
__device__ float g_beta[BATCH][NS];
__device__ float g_Sa[BATCH][NS];

// ---- shared prep logic: from slots (in smem) compute Qk/T/C, zero accumulators ----
// Requires 512 threads, Wsm >= 64*65 floats, red = 24 floats.
__device__ __forceinline__ void dev_prep(
    int b, int t, const float (*sl)[64], float* Wsm,
    float (*sn)[64], float (*q)[64], float* red,
    const float* __restrict__ Wq, const float* __restrict__ bq,
    const float* __restrict__ Wk, const float* __restrict__ bk,
    const float* __restrict__ ln_s_w, const float* __restrict__ ln_s_b,
    const float* __restrict__ ln_in_w, const float* __restrict__ ln_in_b)
{
    float* bkq = red; float* ts = red + 8; float* cs = red + 16;
    if (t < 8) { bkq[t] = 0.f; ts[t] = 0.f; cs[t] = 0.f; }
    int w = t >> 5, lane = t & 31;
    if (w < 8) {
        float v0 = sl[w][lane], v1 = sl[w][lane + 32];
        float s = v0 + v1, s2 = v0 * v0 + v1 * v1;
        #pragma unroll
        for (int k = 16; k >= 1; k >>= 1) {
            s  += __shfl_xor_sync(0xffffffffu, s,  k);
            s2 += __shfl_xor_sync(0xffffffffu, s2, k);
        }
        float mu = s * (1.f / 64.f);
        float rstd = rsqrtf(s2 * (1.f / 64.f) - mu * mu + LN_EPS);
        sn[w][lane]      = (v0 - mu) * rstd * ln_s_w[lane]      + ln_s_b[lane];
        sn[w][lane + 32] = (v1 - mu) * rstd * ln_s_w[lane + 32] + ln_s_b[lane + 32];
    }
    // stage Wq [64][64] via float4 -> stride 65
    for (int i = t; i < 1024; i += 512) {
        float4 v = ((const float4*)Wq)[i];
        int r = i >> 4, c = (i & 15) << 2;
        float* p = &Wsm[r * 65 + c];
        p[0] = v.x; p[1] = v.y; p[2] = v.z; p[3] = v.w;
    }
    __syncthreads();
    {
        int j = t >> 6, a = t & 63;
        float acc = bq[a];
        const float* wr = &Wsm[a * 65];
        #pragma unroll 16
        for (int c = 0; c < 64; c++) acc += sn[j][c] * wr[c];
        q[j][a] = acc;
        atomicAdd(&bkq[j], bk[a] * acc);
    }
    __syncthreads();
    for (int i = t; i < 1024; i += 512) {
        float4 v = ((const float4*)Wk)[i];
        int r = i >> 4, c = (i & 15) << 2;
        float* p = &Wsm[r * 65 + c];
        p[0] = v.x; p[1] = v.y; p[2] = v.z; p[3] = v.w;
    }
    __syncthreads();
    {
        int j = t >> 6, c = t & 63;
        float acc = 0.f;
        #pragma unroll 16
        for (int a = 0; a < 64; a++) acc += Wsm[a * 65 + c] * q[j][a];
        float Qkv = SCALE * ln_in_w[c] * acc;
        g_Qk[b][j][c] = Qkv;
        atomicAdd(&ts[j], Qkv);
        atomicAdd(&cs[j], SCALE * ln_in_b[c] * acc);
    }
    ((float*)g_Z[b])[t] = 0.f;
    __syncthreads();
    if (t < 8) {
        g_T[b][t] = ts[t];
        g_C[b][t] = cs[t] + SCALE * bkq[t];
        g_beta[b][t] = 0.f;
        g_Sa[b][t]   = 0.f;
    }
}

// ---- init slots + prep for iteration 0 ----
__global__ void __launch_bounds__(512) k_init_prep(
    const float* __restrict__ noise, const float* __restrict__ smu,
    const float* __restrict__ ssig,
    const float* __restrict__ Wq, const float* __restrict__ bq,
    const float* __restrict__ Wk, const float* __restrict__ bk,
    const float* __restrict__ ln_s_w, const float* __restrict__ ln_s_b,
    const float* __restrict__ ln_in_w, const float* __restrict__ ln_in_b)
{
    __shared__ float sl[NS][64], sn[NS][64], q[NS][64], red[24];
    extern __shared__ float Wsm[];
    int b = blockIdx.x, t = threadIdx.x;
    int c = t & 63;
    float v = smu[c] + ssig[c] * noise[b * 512 + t];
    sl[t >> 6][c] = v;
    ((float*)g_slots[b])[t] = v;
    __syncthreads();
    dev_prep(b, t, sl, Wsm, sn, q, red, Wq, bq, Wk, bk, ln_s_w, ln_s_b, ln_in_w, ln_in_b);
}

// ---- heavy pass: grid(16, BATCH), 128 threads; masked rows skipped entirely ----
__global__ void __launch_bounds__(128) k_stream(
    const float* __restrict__ inputs, const int* __restrict__ mask)
{
    __shared__ __align__(16) float4 Qk4[NS][16];
    __shared__ float T_s[NS], C_s[NS];
    __shared__ __align__(16) float x_s[128 * 66];
    __shared__ __align__(16) float alphaT[NS][132];
    __shared__ float Zred[NS][64];
    __shared__ float Sa_red[NS], Be_red[NS];

    int b = blockIdx.y, chunk = blockIdx.x, t = threadIdx.x;
    int w = t >> 5, lane = t & 31;

    {
        const float4* qg = (const float4*)&g_Qk[b][0][0];
        ((float4*)Qk4)[t] = qg[t];
        if (t < 8) { T_s[t] = g_T[b][t]; C_s[t] = g_C[b][t]; }
    }
    for (int i = t; i < 512; i += 128) ((float*)Zred)[i] = 0.f;
    if (t < 8) { Sa_red[t] = 0.f; Be_red[t] = 0.f; }
    __syncthreads();

    float sa_acc[8], be_acc[8], z0[8], z1[8];
    #pragma unroll
    for (int j = 0; j < 8; j++) { sa_acc[j] = 0.f; be_acc[j] = 0.f; z0[j] = 0.f; z1[j] = 0.f; }

    #pragma unroll 1
    for (int tile = 0; tile < 2; tile++) {
        int row = chunk * 256 + tile * 128 + t;
        int mv = mask[(size_t)b * NTOK + row];
        float* xrow = &x_s[t * 66];
        if (mv) {
            const float4* xp = (const float4*)(inputs + ((size_t)b * NTOK + row) * 64);
            float s = 0.f, s2 = 0.f;
            float d[8];
            #pragma unroll
            for (int j = 0; j < 8; j++) d[j] = 0.f;
            #pragma unroll
            for (int i = 0; i < 16; i++) {
                float4 v = xp[i];
                s  += (v.x + v.y) + (v.z + v.w);
                s2 += v.x * v.x + v.y * v.y + v.z * v.z + v.w * v.w;
                ((float2*)xrow)[2 * i]     = make_float2(v.x, v.y);
                ((float2*)xrow)[2 * i + 1] = make_float2(v.z, v.w);
                #pragma unroll
                for (int j = 0; j < 8; j++) {
                    float4 qk = Qk4[j][i];
                    d[j] += v.x * qk.x;
                    d[j] += v.y * qk.y;
                    d[j] += v.z * qk.z;
                    d[j] += v.w * qk.w;
                }
            }
            float mu = s * (1.f / 64.f);
            float rstd = rsqrtf(s2 * (1.f / 64.f) - mu * mu + LN_EPS);
            #pragma unroll
            for (int j = 0; j < 8; j++) d[j] = rstd * (d[j] - mu * T_s[j]) + C_s[j];
            float mx = d[0];
            #pragma unroll
            for (int j = 1; j < 8; j++) mx = fmaxf(mx, d[j]);
            float e[8], se = 0.f;
            #pragma unroll
            for (int j = 0; j < 8; j++) { e[j] = __expf(d[j] - mx); se += e[j]; }
            float inv = __fdividef(1.f, se);
            #pragma unroll
            for (int j = 0; j < 8; j++) {
                float a  = e[j] * inv + EPSV;
                float al = a * rstd;
                sa_acc[j] += a;
                be_acc[j] += al * mu;
                alphaT[j][t] = al;
            }
        } else {
            // masked: zero contribution; zero x row so 0*garbage can't produce NaN
            float2 zz = make_float2(0.f, 0.f);
            #pragma unroll
            for (int i = 0; i < 32; i++) ((float2*)xrow)[i] = zz;
            #pragma unroll
            for (int j = 0; j < 8; j++) alphaT[j][t] = 0.f;
        }
        __syncthreads();

        for (int r0 = w * 32; r0 < w * 32 + 32; r0 += 4) {
            float a0[8], a1[8], a2[8], a3[8];
            #pragma unroll
            for (int j = 0; j < 8; j++) {
                float4 av = *(const float4*)&alphaT[j][r0];
                a0[j] = av.x; a1[j] = av.y; a2[j] = av.z; a3[j] = av.w;
            }
            float2 x0 = *(const float2*)&x_s[(r0 + 0) * 66 + 2 * lane];
            float2 x1 = *(const float2*)&x_s[(r0 + 1) * 66 + 2 * lane];
            float2 x2 = *(const float2*)&x_s[(r0 + 2) * 66 + 2 * lane];
            float2 x3 = *(const float2*)&x_s[(r0 + 3) * 66 + 2 * lane];
            #pragma unroll
            for (int j = 0; j < 8; j++) {
                z0[j] += a0[j] * x0.x; z1[j] += a0[j] * x0.y;
                z0[j] += a1[j] * x1.x; z1[j] += a1[j] * x1.y;
                z0[j] += a2[j] * x2.x; z1[j] += a2[j] * x2.y;
                z0[j] += a3[j] * x3.x; z1[j] += a3[j] * x3.y;
            }
        }
        __syncthreads();
    }

    #pragma unroll
    for (int j = 0; j < 8; j++) {
        atomicAdd(&Zred[j][2 * lane],     z0[j]);
        atomicAdd(&Zred[j][2 * lane + 1], z1[j]);
        atomicAdd(&Sa_red[j], sa_acc[j]);
        atomicAdd(&Be_red[j], be_acc[j]);
    }
    __syncthreads();
    for (int i = t; i < 512; i += 128) atomicAdd(&((float*)g_Z[b])[i], ((float*)Zred)[i]);
    if (t < 8) {
        atomicAdd(&g_Sa[b][t],   Sa_red[t]);
        atomicAdd(&g_beta[b][t], Be_red[t]);
    }
}

// ---- update (GRU + MLP) fused with next iteration's prep; 512 threads ----
__global__ void __launch_bounds__(512) k_upd_prep(
    const float* __restrict__ Wv,  const float* __restrict__ bv,
    const float* __restrict__ W_ih, const float* __restrict__ b_ih,
    const float* __restrict__ W_hh, const float* __restrict__ b_hh,
    const float* __restrict__ W1,  const float* __restrict__ b1,
    const float* __restrict__ W2,  const float* __restrict__ b2,
    const float* __restrict__ ln_in_w, const float* __restrict__ ln_in_b,
    const float* __restrict__ ln_ff_w, const float* __restrict__ ln_ff_b,
    const float* __restrict__ Wq, const float* __restrict__ bq,
    const float* __restrict__ Wk, const float* __restrict__ bk,
    const float* __restrict__ ln_s_w, const float* __restrict__ ln_s_b,
    float* __restrict__ out, int last)
{
    extern __shared__ float Wsm[];          // 192*65 floats = 49920 B
    __shared__ float Y_s[NS][64];
    __shared__ float sl_s[NS][64];
    __shared__ float upd_s[NS][64];
    __shared__ float gx_s[NS][192];
    __shared__ float gh_s[NS][192];
    __shared__ float sn_s[NS][64];
    __shared__ float ff_s[NS][64];
    __shared__ float h1_s[NS][128];
    __shared__ float Sa_s[NS], Be_s[NS];
    __shared__ float red[24];

    int b = blockIdx.x, t = threadIdx.x;
    if (t < 8) { Sa_s[t] = g_Sa[b][t]; Be_s[t] = g_beta[b][t]; }
    ((float*)sl_s)[t] = ((const float*)g_slots[b])[t];
    // stage Wv [64][64]
    for (int i = t; i < 1024; i += 512) {
        float4 v = ((const float4*)Wv)[i];
        int r = i >> 4, c = (i & 15) << 2;
        float* p = &Wsm[r * 65 + c];
        p[0] = v.x; p[1] = v.y; p[2] = v.z; p[3] = v.w;
    }
    __syncthreads();

    {
        int j = t >> 6, c = t & 63;
        Y_s[j][c] = ln_in_w[c] * (g_Z[b][j][c] - Be_s[j]) + ln_in_b[c] * Sa_s[j];
    }
    __syncthreads();

    {
        int j = t >> 6, dv = t & 63;
        float acc = 0.f;
        const float* wr = &Wsm[dv * 65];
        #pragma unroll 16
        for (int c = 0; c < 64; c++) acc += wr[c] * Y_s[j][c];
        upd_s[j][dv] = acc * __fdividef(1.f, Sa_s[j]) + bv[dv];
    }
    __syncthreads();

    // W_ih [192][64]
    for (int i = t; i < 3072; i += 512) {
        float4 v = ((const float4*)W_ih)[i];
        int r = i >> 4, c = (i & 15) << 2;
        float* p = &Wsm[r * 65 + c];
        p[0] = v.x; p[1] = v.y; p[2] = v.z; p[3] = v.w;
    }
    __syncthreads();
    #pragma unroll
    for (int kk = 0; kk < 3; kk++) {
        int o = t + kk * 512, j = o / 192, g = o % 192;
        float ax = b_ih[g];
        const float* wx = &Wsm[g * 65];
        #pragma unroll 16
        for (int dd = 0; dd < 64; dd++) ax += wx[dd] * upd_s[j][dd];
        gx_s[j][g] = ax;
    }
    __syncthreads();

    // W_hh [192][64]
    for (int i = t; i < 3072; i += 512) {
        float4 v = ((const float4*)W_hh)[i];
        int r = i >> 4, c = (i & 15) << 2;
        float* p = &Wsm[r * 65 + c];
        p[0] = v.x; p[1] = v.y; p[2] = v.z; p[3] = v.w;
    }
    __syncthreads();
    #pragma unroll
    for (int kk = 0; kk < 3; kk++) {
        int o = t + kk * 512, j = o / 192, g = o % 192;
        float ah = b_hh[g];
        const float* wh = &Wsm[g * 65];
        #pragma unroll 16
        for (int dd = 0; dd < 64; dd++) ah += wh[dd] * sl_s[j][dd];
        gh_s[j][g] = ah;
    }
    __syncthreads();

    {
        int j = t >> 6, dd = t & 63;
        float r = 1.f / (1.f + __expf(-(gx_s[j][dd] + gh_s[j][dd])));
        float z = 1.f / (1.f + __expf(-(gx_s[j][64 + dd] + gh_s[j][64 + dd])));
        float nn = tanhf(gx_s[j][128 + dd] + r * gh_s[j][128 + dd]);
        sn_s[j][dd] = (1.f - z) * nn + z * sl_s[j][dd];
    }
    __syncthreads();

    // LN(ff) by warps 0-7; W1 staging by all threads in parallel
    {
        int wj = t >> 5, lane = t & 31;
        if (wj < 8) {
            float v0 = sn_s[wj][lane], v1 = sn_s[wj][lane + 32];
            float s = v0 + v1, s2 = v0 * v0 + v1 * v1;
            #pragma unroll
            for (int k = 16; k >= 1; k >>= 1) {
                s  += __shfl_xor_sync(0xffffffffu, s,  k);
                s2 += __shfl_xor_sync(0xffffffffu, s2, k);
            }
            float mu = s * (1.f / 64.f);
            float rstd = rsqrtf(s2 * (1.f / 64.f) - mu * mu + LN_EPS);
            ff_s[wj][lane]      = (v0 - mu) * rstd * ln_ff_w[lane]      + ln_ff_b[lane];
            ff_s[wj][lane + 32] = (v1 - mu) * rstd * ln_ff_w[lane + 32] + ln_ff_b[lane + 32];
        }
    }
    for (int i = t; i < 2048; i += 512) {
        float4 v = ((const float4*)W1)[i];
        int r = i >> 4, c = (i & 15) << 2;
        float* p = &Wsm[r * 65 + c];
        p[0] = v.x; p[1] = v.y; p[2] = v.z; p[3] = v.w;
    }
    __syncthreads();

    #pragma unroll
    for (int kk = 0; kk < 2; kk++) {
        int o = t + kk * 512, j = o >> 7, ee = o & 127;
        float acc = b1[ee];
        const float* w1r = &Wsm[ee * 65];
        #pragma unroll 16
        for (int dd = 0; dd < 64; dd++) acc += w1r[dd] * ff_s[j][dd];
        h1_s[j][ee] = fmaxf(acc, 0.f);
    }
    __syncthreads();

    // W2 [64][128] -> stride 129
    for (int i = t; i < 2048; i += 512) {
        float4 v = ((const float4*)W2)[i];
        int r = i >> 5, c = (i & 31) << 2;
        float* p = &Wsm[r * 129 + c];
        p[0] = v.x; p[1] = v.y; p[2] = v.z; p[3] = v.w;
    }
    __syncthreads();

    {
        int j = t >> 6, dd = t & 63;
        float acc = b2[dd];
        const float* w2r = &Wsm[dd * 129];
        #pragma unroll 16
        for (int e = 0; e < 128; e++) acc += w2r[e] * h1_s[j][e];
        float val = sn_s[j][dd] + acc;
        sl_s[j][dd] = val;
        g_slots[b][j][dd] = val;
        if (last) out[(size_t)b * 512 + t] = val;
    }
    __syncthreads();

    if (!last)
        dev_prep(b, t, sl_s, Wsm, ff_s, Y_s, red, Wq, bq, Wk, bk,
                 ln_s_w, ln_s_b, ln_in_w, ln_in_b);
}

extern "C" void kernel_launch(void* const* d_in, const int* in_sizes, int n_in,
                              void* d_out, int out_size)
{
    const float* inputs = (const float*)d_in[0];
    const int*   mask   = (const int*)  d_in[1];
    const float* noise  = (const float*)d_in[2];
    const float* smu    = (const float*)d_in[3];
    const float* ssig   = (const float*)d_in[4];
    const float* Wq = (const float*)d_in[5];  const float* bq = (const float*)d_in[6];
    const float* Wk = (const float*)d_in[7];  const float* bk = (const float*)d_in[8];
    const float* Wv = (const float*)d_in[9];  const float* bv = (const float*)d_in[10];
    const float* W_ih = (const float*)d_in[11]; const float* b_ih = (const float*)d_in[12];
    const float* W_hh = (const float*)d_in[13]; const float* b_hh = (const float*)d_in[14];
    const float* W1 = (const float*)d_in[15]; const float* b1 = (const float*)d_in[16];
    const float* W2 = (const float*)d_in[17]; const float* b2 = (const float*)d_in[18];
    const float* ln_in_w = (const float*)d_in[19]; const float* ln_in_b = (const float*)d_in[20];
    const float* ln_s_w  = (const float*)d_in[21]; const float* ln_s_b  = (const float*)d_in[22];
    const float* ln_ff_w = (const float*)d_in[23]; const float* ln_ff_b = (const float*)d_in[24];
    float* out = (float*)d_out;

    static int smem_set = 0;
    if (!smem_set) {
        cudaFuncSetAttribute(k_upd_prep, cudaFuncAttributeMaxDynamicSharedMemorySize,
                             192 * 65 * (int)sizeof(float));
        cudaFuncSetAttribute(k_init_prep, cudaFuncAttributeMaxDynamicSharedMemorySize,
                             64 * 65 * (int)sizeof(float));
        smem_set = 1;
    }
    const int dynU = 192 * 65 * (int)sizeof(float);
    const int dynI = 64 * 65 * (int)sizeof(float);

    k_init_prep<<<BATCH, 512, dynI>>>(noise, smu, ssig, Wq, bq, Wk, bk,
                                      ln_s_w, ln_s_b, ln_in_w, ln_in_b);
    for (int it = 0; it < 3; it++) {
        k_stream<<<dim3(16, BATCH), 128>>>(inputs, mask);
        k_upd_prep<<<BATCH, 512, dynU>>>(Wv, bv, W_ih, b_ih, W_hh, b_hh, W1, b1, W2, b2,
                                         ln_in_w, ln_in_b, ln_ff_w, ln_ff_b,
                                         Wq, bq, Wk, bk, ln_s_w, ln_s_b,
                                         out, it == 2);
    }
}

// round 11
// speedup vs baseline: 1.6412x; 1.6412x over previous
#include <cuda_runtime.h>
#include <math.h>

#define BATCH 64
#define NTOK  4096
#define NS    8
#define SCALE 0.125f
#define EPSV  1e-8f
#define LN_EPS 1e-5f

__device__ float g_slots[BATCH][NS][64];
__device__ float g_Qk[BATCH][NS][64];
__device__ float g_T[BATCH][NS];
__device__ float g_C[BATCH][NS];
__device__ float g_Z[BATCH][NS][64];
__device__ float g_beta[BATCH][NS];
__device__ float g_Sa[BATCH][NS];

// ---- shared prep logic (512 threads, Wsm >= 64*65 floats, red = 24 floats) ----
__device__ __forceinline__ void dev_prep(
    int b, int t, const float (*sl)[64], float* Wsm,
    float (*sn)[64], float (*q)[64], float* red,
    const float* __restrict__ Wq, const float* __restrict__ bq,
    const float* __restrict__ Wk, const float* __restrict__ bk,
    const float* __restrict__ ln_s_w, const float* __restrict__ ln_s_b,
    const float* __restrict__ ln_in_w, const float* __restrict__ ln_in_b)
{
    float* bkq = red; float* ts = red + 8; float* cs = red + 16;
    if (t < 8) { bkq[t] = 0.f; ts[t] = 0.f; cs[t] = 0.f; }
    int w = t >> 5, lane = t & 31;
    if (w < 8) {
        float v0 = sl[w][lane], v1 = sl[w][lane + 32];
        float s = v0 + v1, s2 = v0 * v0 + v1 * v1;
        #pragma unroll
        for (int k = 16; k >= 1; k >>= 1) {
            s  += __shfl_xor_sync(0xffffffffu, s,  k);
            s2 += __shfl_xor_sync(0xffffffffu, s2, k);
        }
        float mu = s * (1.f / 64.f);
        float rstd = rsqrtf(s2 * (1.f / 64.f) - mu * mu + LN_EPS);
        sn[w][lane]      = (v0 - mu) * rstd * ln_s_w[lane]      + ln_s_b[lane];
        sn[w][lane + 32] = (v1 - mu) * rstd * ln_s_w[lane + 32] + ln_s_b[lane + 32];
    }
    for (int i = t; i < 1024; i += 512) {
        float4 v = ((const float4*)Wq)[i];
        int r = i >> 4, c = (i & 15) << 2;
        float* p = &Wsm[r * 65 + c];
        p[0] = v.x; p[1] = v.y; p[2] = v.z; p[3] = v.w;
    }
    __syncthreads();
    {
        int j = t >> 6, a = t & 63;
        float acc = bq[a];
        const float* wr = &Wsm[a * 65];
        #pragma unroll 16
        for (int c = 0; c < 64; c++) acc += sn[j][c] * wr[c];
        q[j][a] = acc;
        atomicAdd(&bkq[j], bk[a] * acc);
    }
    __syncthreads();
    for (int i = t; i < 1024; i += 512) {
        float4 v = ((const float4*)Wk)[i];
        int r = i >> 4, c = (i & 15) << 2;
        float* p = &Wsm[r * 65 + c];
        p[0] = v.x; p[1] = v.y; p[2] = v.z; p[3] = v.w;
    }
    __syncthreads();
    {
        int j = t >> 6, c = t & 63;
        float acc = 0.f;
        #pragma unroll 16
        for (int a = 0; a < 64; a++) acc += Wsm[a * 65 + c] * q[j][a];
        float Qkv = SCALE * ln_in_w[c] * acc;
        g_Qk[b][j][c] = Qkv;
        atomicAdd(&ts[j], Qkv);
        atomicAdd(&cs[j], SCALE * ln_in_b[c] * acc);
    }
    ((float*)g_Z[b])[t] = 0.f;
    __syncthreads();
    if (t < 8) {
        g_T[b][t] = ts[t];
        g_C[b][t] = cs[t] + SCALE * bkq[t];
        g_beta[b][t] = 0.f;
        g_Sa[b][t]   = 0.f;
    }
}

__global__ void __launch_bounds__(512) k_init_prep(
    const float* __restrict__ noise, const float* __restrict__ smu,
    const float* __restrict__ ssig,
    const float* __restrict__ Wq, const float* __restrict__ bq,
    const float* __restrict__ Wk, const float* __restrict__ bk,
    const float* __restrict__ ln_s_w, const float* __restrict__ ln_s_b,
    const float* __restrict__ ln_in_w, const float* __restrict__ ln_in_b)
{
    __shared__ float sl[NS][64], sn[NS][64], q[NS][64], red[24];
    extern __shared__ float Wsm[];
    int b = blockIdx.x, t = threadIdx.x;
    int c = t & 63;
    float v = smu[c] + ssig[c] * noise[b * 512 + t];
    sl[t >> 6][c] = v;
    ((float*)g_slots[b])[t] = v;
    __syncthreads();
    dev_prep(b, t, sl, Wsm, sn, q, red, Wq, bq, Wk, bk, ln_s_w, ln_s_b, ln_in_w, ln_in_b);
}

// ---- heavy pass: grid(16, BATCH), 128 threads ----
// KEY FIX vs prior rounds: global->smem tile copy is COALESCED (4 wavefronts/LDG,
// was 32: thread-per-row transposed access). Phase A reads rows from smem
// (stride 68 floats: LDS.128 conflict-free in 8-lane phases). Branchless mask.
#define XST 68
__global__ void __launch_bounds__(128) k_stream(
    const float* __restrict__ inputs, const int* __restrict__ mask)
{
    __shared__ __align__(16) float4 Qk4[NS][16];
    __shared__ float T_s[NS], C_s[NS];
    __shared__ __align__(16) float x_s[128 * XST];
    __shared__ __align__(16) float alphaT[NS][132];
    __shared__ float Zred[NS][64];
    __shared__ float Sa_red[NS], Be_red[NS];

    int b = blockIdx.y, chunk = blockIdx.x, t = threadIdx.x;
    int w = t >> 5, lane = t & 31;

    {
        const float4* qg = (const float4*)&g_Qk[b][0][0];
        ((float4*)Qk4)[t] = qg[t];
        if (t < 8) { T_s[t] = g_T[b][t]; C_s[t] = g_C[b][t]; }
    }
    for (int i = t; i < 512; i += 128) ((float*)Zred)[i] = 0.f;
    if (t < 8) { Sa_red[t] = 0.f; Be_red[t] = 0.f; }
    __syncthreads();

    float sa_acc[8], be_acc[8], z0[8], z1[8];
    #pragma unroll
    for (int j = 0; j < 8; j++) { sa_acc[j] = 0.f; be_acc[j] = 0.f; z0[j] = 0.f; z1[j] = 0.f; }

    #pragma unroll 1
    for (int tile = 0; tile < 2; tile++) {
        int base = chunk * 256 + tile * 128;
        // prefetch this thread's mask value early
        float mval = (mask[(size_t)b * NTOK + base + t] != 0) ? 1.f : 0.f;

        // coalesced tile copy: 128 rows x 64 floats -> x_s (row stride XST)
        {
            const float4* gsrc = (const float4*)(inputs + ((size_t)b * NTOK + base) * 64);
            #pragma unroll
            for (int i = 0; i < 16; i++) {
                int idx = i * 128 + t;
                int r = idx >> 4, ic = idx & 15;
                ((float4*)x_s)[r * (XST / 4) + ic] = gsrc[idx];
            }
        }
        __syncthreads();

        // ---- phase A: thread t processes row t from smem ----
        {
            const float4* xrow = (const float4*)&x_s[t * XST];
            float s = 0.f, s2 = 0.f;
            float d[8];
            #pragma unroll
            for (int j = 0; j < 8; j++) d[j] = 0.f;
            #pragma unroll
            for (int i = 0; i < 16; i++) {
                float4 v = xrow[i];
                s  += (v.x + v.y) + (v.z + v.w);
                s2 += v.x * v.x + v.y * v.y + v.z * v.z + v.w * v.w;
                #pragma unroll
                for (int j = 0; j < 8; j++) {
                    float4 qk = Qk4[j][i];
                    d[j] += v.x * qk.x;
                    d[j] += v.y * qk.y;
                    d[j] += v.z * qk.z;
                    d[j] += v.w * qk.w;
                }
            }
            float mu = s * (1.f / 64.f);
            float rstd = rsqrtf(s2 * (1.f / 64.f) - mu * mu + LN_EPS);
            #pragma unroll
            for (int j = 0; j < 8; j++) d[j] = rstd * (d[j] - mu * T_s[j]) + C_s[j];
            float mx = d[0];
            #pragma unroll
            for (int j = 1; j < 8; j++) mx = fmaxf(mx, d[j]);
            float e[8], se = 0.f;
            #pragma unroll
            for (int j = 0; j < 8; j++) { e[j] = __expf(d[j] - mx); se += e[j]; }
            float inv = __fdividef(1.f, se) * mval;
            #pragma unroll
            for (int j = 0; j < 8; j++) {
                float a  = e[j] * inv + EPSV * mval;
                float al = a * rstd;
                sa_acc[j] += a;
                be_acc[j] += al * mu;
                alphaT[j][t] = al;
            }
        }
        __syncthreads();

        // ---- phase B: warp w -> rows [32w, 32w+32); lane -> channels 2*lane, 2*lane+1
        for (int r0 = w * 32; r0 < w * 32 + 32; r0 += 4) {
            float a0[8], a1[8], a2[8], a3[8];
            #pragma unroll
            for (int j = 0; j < 8; j++) {
                float4 av = *(const float4*)&alphaT[j][r0];
                a0[j] = av.x; a1[j] = av.y; a2[j] = av.z; a3[j] = av.w;
            }
            float2 x0 = *(const float2*)&x_s[(r0 + 0) * XST + 2 * lane];
            float2 x1 = *(const float2*)&x_s[(r0 + 1) * XST + 2 * lane];
            float2 x2 = *(const float2*)&x_s[(r0 + 2) * XST + 2 * lane];
            float2 x3 = *(const float2*)&x_s[(r0 + 3) * XST + 2 * lane];
            #pragma unroll
            for (int j = 0; j < 8; j++) {
                z0[j] += a0[j] * x0.x; z1[j] += a0[j] * x0.y;
                z0[j] += a1[j] * x1.x; z1[j] += a1[j] * x1.y;
                z0[j] += a2[j] * x2.x; z1[j] += a2[j] * x2.y;
                z0[j] += a3[j] * x3.x; z1[j] += a3[j] * x3.y;
            }
        }
        __syncthreads();
    }

    #pragma unroll
    for (int j = 0; j < 8; j++) {
        atomicAdd(&Zred[j][2 * lane],     z0[j]);
        atomicAdd(&Zred[j][2 * lane + 1], z1[j]);
        atomicAdd(&Sa_red[j], sa_acc[j]);
        atomicAdd(&Be_red[j], be_acc[j]);
    }
    __syncthreads();
    for (int i = t; i < 512; i += 128) atomicAdd(&((float*)g_Z[b])[i], ((float*)Zred)[i]);
    if (t < 8) {
        atomicAdd(&g_Sa[b][t],   Sa_red[t]);
        atomicAdd(&g_beta[b][t], Be_red[t]);
    }
}

// ---- update (GRU + MLP) fused with next iteration's prep; 512 threads ----
__global__ void __launch_bounds__(512) k_upd_prep(
    const float* __restrict__ Wv,  const float* __restrict__ bv,
    const float* __restrict__ W_ih, const float* __restrict__ b_ih,
    const float* __restrict__ W_hh, const float* __restrict__ b_hh,
    const float* __restrict__ W1,  const float* __restrict__ b1,
    const float* __restrict__ W2,  const float* __restrict__ b2,
    const float* __restrict__ ln_in_w, const float* __restrict__ ln_in_b,
    const float* __restrict__ ln_ff_w, const float* __restrict__ ln_ff_b,
    const float* __restrict__ Wq, const float* __restrict__ bq,
    const float* __restrict__ Wk, const float* __restrict__ bk,
    const float* __restrict__ ln_s_w, const float* __restrict__ ln_s_b,
    float* __restrict__ out, int last)
{
    extern __shared__ float Wsm[];          // 192*65 floats = 49920 B
    __shared__ float Y_s[NS][64];
    __shared__ float sl_s[NS][64];
    __shared__ float upd_s[NS][64];
    __shared__ float gx_s[NS][192];
    __shared__ float gh_s[NS][192];
    __shared__ float sn_s[NS][64];
    __shared__ float ff_s[NS][64];
    __shared__ float h1_s[NS][128];
    __shared__ float Sa_s[NS], Be_s[NS];
    __shared__ float red[24];

    int b = blockIdx.x, t = threadIdx.x;
    if (t < 8) { Sa_s[t] = g_Sa[b][t]; Be_s[t] = g_beta[b][t]; }
    ((float*)sl_s)[t] = ((const float*)g_slots[b])[t];
    for (int i = t; i < 1024; i += 512) {
        float4 v = ((const float4*)Wv)[i];
        int r = i >> 4, c = (i & 15) << 2;
        float* p = &Wsm[r * 65 + c];
        p[0] = v.x; p[1] = v.y; p[2] = v.z; p[3] = v.w;
    }
    __syncthreads();

    {
        int j = t >> 6, c = t & 63;
        Y_s[j][c] = ln_in_w[c] * (g_Z[b][j][c] - Be_s[j]) + ln_in_b[c] * Sa_s[j];
    }
    __syncthreads();

    {
        int j = t >> 6, dv = t & 63;
        float acc = 0.f;
        const float* wr = &Wsm[dv * 65];
        #pragma unroll 16
        for (int c = 0; c < 64; c++) acc += wr[c] * Y_s[j][c];
        upd_s[j][dv] = acc * __fdividef(1.f, Sa_s[j]) + bv[dv];
    }
    __syncthreads();

    for (int i = t; i < 3072; i += 512) {
        float4 v = ((const float4*)W_ih)[i];
        int r = i >> 4, c = (i & 15) << 2;
        float* p = &Wsm[r * 65 + c];
        p[0] = v.x; p[1] = v.y; p[2] = v.z; p[3] = v.w;
    }
    __syncthreads();
    #pragma unroll
    for (int kk = 0; kk < 3; kk++) {
        int o = t + kk * 512, j = o / 192, g = o % 192;
        float ax = b_ih[g];
        const float* wx = &Wsm[g * 65];
        #pragma unroll 16
        for (int dd = 0; dd < 64; dd++) ax += wx[dd] * upd_s[j][dd];
        gx_s[j][g] = ax;
    }
    __syncthreads();

    for (int i = t; i < 3072; i += 512) {
        float4 v = ((const float4*)W_hh)[i];
        int r = i >> 4, c = (i & 15) << 2;
        float* p = &Wsm[r * 65 + c];
        p[0] = v.x; p[1] = v.y; p[2] = v.z; p[3] = v.w;
    }
    __syncthreads();
    #pragma unroll
    for (int kk = 0; kk < 3; kk++) {
        int o = t + kk * 512, j = o / 192, g = o % 192;
        float ah = b_hh[g];
        const float* wh = &Wsm[g * 65];
        #pragma unroll 16
        for (int dd = 0; dd < 64; dd++) ah += wh[dd] * sl_s[j][dd];
        gh_s[j][g] = ah;
    }
    __syncthreads();

    {
        int j = t >> 6, dd = t & 63;
        float r = 1.f / (1.f + __expf(-(gx_s[j][dd] + gh_s[j][dd])));
        float z = 1.f / (1.f + __expf(-(gx_s[j][64 + dd] + gh_s[j][64 + dd])));
        float nn = tanhf(gx_s[j][128 + dd] + r * gh_s[j][128 + dd]);
        sn_s[j][dd] = (1.f - z) * nn + z * sl_s[j][dd];
    }
    __syncthreads();

    {
        int wj = t >> 5, lane = t & 31;
        if (wj < 8) {
            float v0 = sn_s[wj][lane], v1 = sn_s[wj][lane + 32];
            float s = v0 + v1, s2 = v0 * v0 + v1 * v1;
            #pragma unroll
            for (int k = 16; k >= 1; k >>= 1) {
                s  += __shfl_xor_sync(0xffffffffu, s,  k);
                s2 += __shfl_xor_sync(0xffffffffu, s2, k);
            }
            float mu = s * (1.f / 64.f);
            float rstd = rsqrtf(s2 * (1.f / 64.f) - mu * mu + LN_EPS);
            ff_s[wj][lane]      = (v0 - mu) * rstd * ln_ff_w[lane]      + ln_ff_b[lane];
            ff_s[wj][lane + 32] = (v1 - mu) * rstd * ln_ff_w[lane + 32] + ln_ff_b[lane + 32];
        }
    }
    for (int i = t; i < 2048; i += 512) {
        float4 v = ((const float4*)W1)[i];
        int r = i >> 4, c = (i & 15) << 2;
        float* p = &Wsm[r * 65 + c];
        p[0] = v.x; p[1] = v.y; p[2] = v.z; p[3] = v.w;
    }
    __syncthreads();

    #pragma unroll
    for (int kk = 0; kk < 2; kk++) {
        int o = t + kk * 512, j = o >> 7, ee = o & 127;
        float acc = b1[ee];
        const float* w1r = &Wsm[ee * 65];
        #pragma unroll 16
        for (int dd = 0; dd < 64; dd++) acc += w1r[dd] * ff_s[j][dd];
        h1_s[j][ee] = fmaxf(acc, 0.f);
    }
    __syncthreads();

    for (int i = t; i < 2048; i += 512) {
        float4 v = ((const float4*)W2)[i];
        int r = i >> 5, c = (i & 31) << 2;
        float* p = &Wsm[r * 129 + c];
        p[0] = v.x; p[1] = v.y; p[2] = v.z; p[3] = v.w;
    }
    __syncthreads();

    {
        int j = t >> 6, dd = t & 63;
        float acc = b2[dd];
        const float* w2r = &Wsm[dd * 129];
        #pragma unroll 16
        for (int e = 0; e < 128; e++) acc += w2r[e] * h1_s[j][e];
        float val = sn_s[j][dd] + acc;
        sl_s[j][dd] = val;
        g_slots[b][j][dd] = val;
        if (last) out[(size_t)b * 512 + t] = val;
    }
    __syncthreads();

    if (!last)
        dev_prep(b, t, sl_s, Wsm, ff_s, Y_s, red, Wq, bq, Wk, bk,
                 ln_s_w, ln_s_b, ln_in_w, ln_in_b);
}

extern "C" void kernel_launch(void* const* d_in, const int* in_sizes, int n_in,
                              void* d_out, int out_size)
{
    const float* inputs = (const float*)d_in[0];
    const int*   mask   = (const int*)  d_in[1];
    const float* noise  = (const float*)d_in[2];
    const float* smu    = (const float*)d_in[3];
    const float* ssig   = (const float*)d_in[4];
    const float* Wq = (const float*)d_in[5];  const float* bq = (const float*)d_in[6];
    const float* Wk = (const float*)d_in[7];  const float* bk = (const float*)d_in[8];
    const float* Wv = (const float*)d_in[9];  const float* bv = (const float*)d_in[10];
    const float* W_ih = (const float*)d_in[11]; const float* b_ih = (const float*)d_in[12];
    const float* W_hh = (const float*)d_in[13]; const float* b_hh = (const float*)d_in[14];
    const float* W1 = (const float*)d_in[15]; const float* b1 = (const float*)d_in[16];
    const float* W2 = (const float*)d_in[17]; const float* b2 = (const float*)d_in[18];
    const float* ln_in_w = (const float*)d_in[19]; const float* ln_in_b = (const float*)d_in[20];
    const float* ln_s_w  = (const float*)d_in[21]; const float* ln_s_b  = (const float*)d_in[22];
    const float* ln_ff_w = (const float*)d_in[23]; const float* ln_ff_b = (const float*)d_in[24];
    float* out = (float*)d_out;

    static int smem_set = 0;
    if (!smem_set) {
        cudaFuncSetAttribute(k_upd_prep, cudaFuncAttributeMaxDynamicSharedMemorySize,
                             192 * 65 * (int)sizeof(float));
        cudaFuncSetAttribute(k_init_prep, cudaFuncAttributeMaxDynamicSharedMemorySize,
                             64 * 65 * (int)sizeof(float));
        smem_set = 1;
    }
    const int dynU = 192 * 65 * (int)sizeof(float);
    const int dynI = 64 * 65 * (int)sizeof(float);

    k_init_prep<<<BATCH, 512, dynI>>>(noise, smu, ssig, Wq, bq, Wk, bk,
                                      ln_s_w, ln_s_b, ln_in_w, ln_in_b);
    for (int it = 0; it < 3; it++) {
        k_stream<<<dim3(16, BATCH), 128>>>(inputs, mask);
        k_upd_prep<<<BATCH, 512, dynU>>>(Wv, bv, W_ih, b_ih, W_hh, b_hh, W1, b1, W2, b2,
                                         ln_in_w, ln_in_b, ln_ff_w, ln_ff_b,
                                         Wq, bq, Wk, bk, ln_s_w, ln_s_b,
                                         out, it == 2);
    }
}

// round 12
// speedup vs baseline: 3.7113x; 2.2613x over previous
#include <cuda_runtime.h>
#include <math.h>

#define BATCH 64
#define NTOK  4096
#define NS    8
#define SCALE 0.125f
#define EPSV  1e-8f
#define LN_EPS 1e-5f

typedef unsigned long long ull;

__device__ __forceinline__ ull pk2(float x, float y) {
    ull r; asm("mov.b64 %0, {%1, %2};" : "=l"(r) : "f"(x), "f"(y)); return r;
}
__device__ __forceinline__ float2 upk2(ull u) {
    float2 f; asm("mov.b64 {%0, %1}, %2;" : "=f"(f.x), "=f"(f.y) : "l"(u)); return f;
}
#define FMA2(d, a, b) asm("fma.rn.f32x2 %0, %1, %2, %0;" : "+l"(d) : "l"(a), "l"(b))
#define ADD2(d, a)    asm("add.rn.f32x2 %0, %1, %0;" : "+l"(d) : "l"(a))

__device__ float g_slots[BATCH][NS][64];
__device__ float g_Qk[BATCH][NS][64];
__device__ float g_T[BATCH][NS];
__device__ float g_C[BATCH][NS];
__device__ float g_Z[BATCH][NS][64];
__device__ float g_beta[BATCH][NS];
__device__ float g_Sa[BATCH][NS];

// ---- shared prep logic (512 threads, Wsm >= 64*65 floats, red = 24 floats) ----
__device__ __forceinline__ void dev_prep(
    int b, int t, const float (*sl)[64], float* Wsm,
    float (*sn)[64], float (*q)[64], float* red,
    const float* __restrict__ Wq, const float* __restrict__ bq,
    const float* __restrict__ Wk, const float* __restrict__ bk,
    const float* __restrict__ ln_s_w, const float* __restrict__ ln_s_b,
    const float* __restrict__ ln_in_w, const float* __restrict__ ln_in_b)
{
    float* bkq = red; float* ts = red + 8; float* cs = red + 16;
    if (t < 8) { bkq[t] = 0.f; ts[t] = 0.f; cs[t] = 0.f; }
    int w = t >> 5, lane = t & 31;
    if (w < 8) {
        float v0 = sl[w][lane], v1 = sl[w][lane + 32];
        float s = v0 + v1, s2 = v0 * v0 + v1 * v1;
        #pragma unroll
        for (int k = 16; k >= 1; k >>= 1) {
            s  += __shfl_xor_sync(0xffffffffu, s,  k);
            s2 += __shfl_xor_sync(0xffffffffu, s2, k);
        }
        float mu = s * (1.f / 64.f);
        float rstd = rsqrtf(s2 * (1.f / 64.f) - mu * mu + LN_EPS);
        sn[w][lane]      = (v0 - mu) * rstd * ln_s_w[lane]      + ln_s_b[lane];
        sn[w][lane + 32] = (v1 - mu) * rstd * ln_s_w[lane + 32] + ln_s_b[lane + 32];
    }
    for (int i = t; i < 1024; i += 512) {
        float4 v = ((const float4*)Wq)[i];
        int r = i >> 4, c = (i & 15) << 2;
        float* p = &Wsm[r * 65 + c];
        p[0] = v.x; p[1] = v.y; p[2] = v.z; p[3] = v.w;
    }
    __syncthreads();
    {
        int j = t >> 6, a = t & 63;
        float acc = bq[a];
        const float* wr = &Wsm[a * 65];
        #pragma unroll 16
        for (int c = 0; c < 64; c++) acc += sn[j][c] * wr[c];
        q[j][a] = acc;
        atomicAdd(&bkq[j], bk[a] * acc);
    }
    __syncthreads();
    for (int i = t; i < 1024; i += 512) {
        float4 v = ((const float4*)Wk)[i];
        int r = i >> 4, c = (i & 15) << 2;
        float* p = &Wsm[r * 65 + c];
        p[0] = v.x; p[1] = v.y; p[2] = v.z; p[3] = v.w;
    }
    __syncthreads();
    {
        int j = t >> 6, c = t & 63;
        float acc = 0.f;
        #pragma unroll 16
        for (int a = 0; a < 64; a++) acc += Wsm[a * 65 + c] * q[j][a];
        float Qkv = SCALE * ln_in_w[c] * acc;
        g_Qk[b][j][c] = Qkv;
        atomicAdd(&ts[j], Qkv);
        atomicAdd(&cs[j], SCALE * ln_in_b[c] * acc);
    }
    ((float*)g_Z[b])[t] = 0.f;
    __syncthreads();
    if (t < 8) {
        g_T[b][t] = ts[t];
        g_C[b][t] = cs[t] + SCALE * bkq[t];
        g_beta[b][t] = 0.f;
        g_Sa[b][t]   = 0.f;
    }
}

__global__ void __launch_bounds__(512) k_init_prep(
    const float* __restrict__ noise, const float* __restrict__ smu,
    const float* __restrict__ ssig,
    const float* __restrict__ Wq, const float* __restrict__ bq,
    const float* __restrict__ Wk, const float* __restrict__ bk,
    const float* __restrict__ ln_s_w, const float* __restrict__ ln_s_b,
    const float* __restrict__ ln_in_w, const float* __restrict__ ln_in_b)
{
    __shared__ float sl[NS][64], sn[NS][64], q[NS][64], red[24];
    extern __shared__ float Wsm[];
    int b = blockIdx.x, t = threadIdx.x;
    int c = t & 63;
    float v = smu[c] + ssig[c] * noise[b * 512 + t];
    sl[t >> 6][c] = v;
    ((float*)g_slots[b])[t] = v;
    __syncthreads();
    dev_prep(b, t, sl, Wsm, sn, q, red, Wq, bq, Wk, bk, ln_s_w, ln_s_b, ln_in_w, ln_in_b);
}

// ---- heavy pass: grid(16, BATCH), 128 threads; packed f32x2 math ----
#define XST 68
__global__ void __launch_bounds__(128) k_stream(
    const float* __restrict__ inputs, const int* __restrict__ mask)
{
    __shared__ __align__(16) ulonglong2 Qk2[NS][16];  // Qk rows as packed pairs
    __shared__ float T_s[NS], C_s[NS];
    __shared__ __align__(16) float x_s[128 * XST];
    __shared__ __align__(16) ull alphaT2[NS][128];    // (al, al) duplicated pairs

    int b = blockIdx.y, chunk = blockIdx.x, t = threadIdx.x;
    int w = t >> 5, lane = t & 31;

    {
        const float4* qg = (const float4*)&g_Qk[b][0][0];
        ((float4*)Qk2)[t] = qg[t];
        if (t < 8) { T_s[t] = g_T[b][t]; C_s[t] = g_C[b][t]; }
    }
    __syncthreads();

    float sa_acc[8], be_acc[8];
    ull zp[8];
    #pragma unroll
    for (int j = 0; j < 8; j++) { sa_acc[j] = 0.f; be_acc[j] = 0.f; zp[j] = 0ull; }

    #pragma unroll 1
    for (int tile = 0; tile < 2; tile++) {
        int base = chunk * 256 + tile * 128;
        float mval = (mask[(size_t)b * NTOK + base + t] != 0) ? 1.f : 0.f;

        // coalesced tile copy: 128 rows x 64 floats -> x_s (row stride XST)
        {
            const float4* gsrc = (const float4*)(inputs + ((size_t)b * NTOK + base) * 64);
            #pragma unroll
            for (int i = 0; i < 16; i++) {
                int idx = i * 128 + t;
                int r = idx >> 4, ic = idx & 15;
                ((float4*)x_s)[r * (XST / 4) + ic] = gsrc[idx];
            }
        }
        __syncthreads();

        // ---- phase A: thread t = row t; packed dots ----
        {
            const ulonglong2* xr = (const ulonglong2*)&x_s[t * XST];
            ull dacc[8], sacc = 0ull, s2acc = 0ull;
            #pragma unroll
            for (int j = 0; j < 8; j++) dacc[j] = 0ull;
            #pragma unroll
            for (int i = 0; i < 16; i++) {
                ulonglong2 xv = xr[i];
                ADD2(sacc, xv.x); ADD2(sacc, xv.y);
                FMA2(s2acc, xv.x, xv.x); FMA2(s2acc, xv.y, xv.y);
                #pragma unroll
                for (int j = 0; j < 8; j++) {
                    ulonglong2 qk = Qk2[j][i];
                    FMA2(dacc[j], xv.x, qk.x);
                    FMA2(dacc[j], xv.y, qk.y);
                }
            }
            float2 sf = upk2(sacc), s2f = upk2(s2acc);
            float s = sf.x + sf.y, s2 = s2f.x + s2f.y;
            float mu = s * (1.f / 64.f);
            float rstd = rsqrtf(s2 * (1.f / 64.f) - mu * mu + LN_EPS);
            float d[8];
            #pragma unroll
            for (int j = 0; j < 8; j++) {
                float2 dd = upk2(dacc[j]);
                d[j] = rstd * ((dd.x + dd.y) - mu * T_s[j]) + C_s[j];
            }
            float mx = d[0];
            #pragma unroll
            for (int j = 1; j < 8; j++) mx = fmaxf(mx, d[j]);
            float e[8], se = 0.f;
            #pragma unroll
            for (int j = 0; j < 8; j++) { e[j] = __expf(d[j] - mx); se += e[j]; }
            float inv = __fdividef(1.f, se) * mval;
            float epsm = EPSV * mval;
            #pragma unroll
            for (int j = 0; j < 8; j++) {
                float a  = e[j] * inv + epsm;
                float al = a * rstd;
                sa_acc[j] += a;
                be_acc[j] += al * mu;
                alphaT2[j][t] = pk2(al, al);
            }
        }
        __syncthreads();

        // ---- phase B: warp w -> rows [32w,32w+32); lane -> channels (2lane, 2lane+1) packed
        for (int r0 = w * 32; r0 < w * 32 + 32; r0 += 4) {
            ull x0 = *(const ull*)&x_s[(r0 + 0) * XST + 2 * lane];
            ull x1 = *(const ull*)&x_s[(r0 + 1) * XST + 2 * lane];
            ull x2 = *(const ull*)&x_s[(r0 + 2) * XST + 2 * lane];
            ull x3 = *(const ull*)&x_s[(r0 + 3) * XST + 2 * lane];
            #pragma unroll
            for (int j = 0; j < 8; j++) {
                ulonglong2 aa = *(const ulonglong2*)&alphaT2[j][r0];
                ulonglong2 ab = *(const ulonglong2*)&alphaT2[j][r0 + 2];
                FMA2(zp[j], aa.x, x0);
                FMA2(zp[j], aa.y, x1);
                FMA2(zp[j], ab.x, x2);
                FMA2(zp[j], ab.y, x3);
            }
        }
        __syncthreads();
    }

    // ---- merge: z direct global atomics; sa/be shuffle-reduced per warp ----
    #pragma unroll
    for (int j = 0; j < 8; j++) {
        float2 zz = upk2(zp[j]);
        atomicAdd(&g_Z[b][j][2 * lane],     zz.x);
        atomicAdd(&g_Z[b][j][2 * lane + 1], zz.y);
    }
    #pragma unroll
    for (int j = 0; j < 8; j++) {
        float sv = sa_acc[j], bv2 = be_acc[j];
        #pragma unroll
        for (int k = 16; k >= 1; k >>= 1) {
            sv  += __shfl_xor_sync(0xffffffffu, sv,  k);
            bv2 += __shfl_xor_sync(0xffffffffu, bv2, k);
        }
        if (lane == 0) {
            atomicAdd(&g_Sa[b][j],   sv);
            atomicAdd(&g_beta[b][j], bv2);
        }
    }
}

// ---- update (GRU + MLP) fused with next iteration's prep; 512 threads ----
__global__ void __launch_bounds__(512) k_upd_prep(
    const float* __restrict__ Wv,  const float* __restrict__ bv,
    const float* __restrict__ W_ih, const float* __restrict__ b_ih,
    const float* __restrict__ W_hh, const float* __restrict__ b_hh,
    const float* __restrict__ W1,  const float* __restrict__ b1,
    const float* __restrict__ W2,  const float* __restrict__ b2,
    const float* __restrict__ ln_in_w, const float* __restrict__ ln_in_b,
    const float* __restrict__ ln_ff_w, const float* __restrict__ ln_ff_b,
    const float* __restrict__ Wq, const float* __restrict__ bq,
    const float* __restrict__ Wk, const float* __restrict__ bk,
    const float* __restrict__ ln_s_w, const float* __restrict__ ln_s_b,
    float* __restrict__ out, int last)
{
    extern __shared__ float Wsm[];          // 192*65 floats = 49920 B
    __shared__ float Y_s[NS][64];
    __shared__ float sl_s[NS][64];
    __shared__ float upd_s[NS][64];
    __shared__ float gx_s[NS][192];
    __shared__ float gh_s[NS][192];
    __shared__ float sn_s[NS][64];
    __shared__ float ff_s[NS][64];
    __shared__ float h1_s[NS][128];
    __shared__ float Sa_s[NS], Be_s[NS];
    __shared__ float red[24];

    int b = blockIdx.x, t = threadIdx.x;
    if (t < 8) { Sa_s[t] = g_Sa[b][t]; Be_s[t] = g_beta[b][t]; }
    ((float*)sl_s)[t] = ((const float*)g_slots[b])[t];
    for (int i = t; i < 1024; i += 512) {
        float4 v = ((const float4*)Wv)[i];
        int r = i >> 4, c = (i & 15) << 2;
        float* p = &Wsm[r * 65 + c];
        p[0] = v.x; p[1] = v.y; p[2] = v.z; p[3] = v.w;
    }
    __syncthreads();

    {
        int j = t >> 6, c = t & 63;
        Y_s[j][c] = ln_in_w[c] * (g_Z[b][j][c] - Be_s[j]) + ln_in_b[c] * Sa_s[j];
    }
    __syncthreads();

    {
        int j = t >> 6, dv = t & 63;
        float acc = 0.f;
        const float* wr = &Wsm[dv * 65];
        #pragma unroll 16
        for (int c = 0; c < 64; c++) acc += wr[c] * Y_s[j][c];
        upd_s[j][dv] = acc * __fdividef(1.f, Sa_s[j]) + bv[dv];
    }
    __syncthreads();

    for (int i = t; i < 3072; i += 512) {
        float4 v = ((const float4*)W_ih)[i];
        int r = i >> 4, c = (i & 15) << 2;
        float* p = &Wsm[r * 65 + c];
        p[0] = v.x; p[1] = v.y; p[2] = v.z; p[3] = v.w;
    }
    __syncthreads();
    #pragma unroll
    for (int kk = 0; kk < 3; kk++) {
        int o = t + kk * 512, j = o / 192, g = o % 192;
        float ax = b_ih[g];
        const float* wx = &Wsm[g * 65];
        #pragma unroll 16
        for (int dd = 0; dd < 64; dd++) ax += wx[dd] * upd_s[j][dd];
        gx_s[j][g] = ax;
    }
    __syncthreads();

    for (int i = t; i < 3072; i += 512) {
        float4 v = ((const float4*)W_hh)[i];
        int r = i >> 4, c = (i & 15) << 2;
        float* p = &Wsm[r * 65 + c];
        p[0] = v.x; p[1] = v.y; p[2] = v.z; p[3] = v.w;
    }
    __syncthreads();
    #pragma unroll
    for (int kk = 0; kk < 3; kk++) {
        int o = t + kk * 512, j = o / 192, g = o % 192;
        float ah = b_hh[g];
        const float* wh = &Wsm[g * 65];
        #pragma unroll 16
        for (int dd = 0; dd < 64; dd++) ah += wh[dd] * sl_s[j][dd];
        gh_s[j][g] = ah;
    }
    __syncthreads();

    {
        int j = t >> 6, dd = t & 63;
        float r = 1.f / (1.f + __expf(-(gx_s[j][dd] + gh_s[j][dd])));
        float z = 1.f / (1.f + __expf(-(gx_s[j][64 + dd] + gh_s[j][64 + dd])));
        float nn = tanhf(gx_s[j][128 + dd] + r * gh_s[j][128 + dd]);
        sn_s[j][dd] = (1.f - z) * nn + z * sl_s[j][dd];
    }
    __syncthreads();

    {
        int wj = t >> 5, lane = t & 31;
        if (wj < 8) {
            float v0 = sn_s[wj][lane], v1 = sn_s[wj][lane + 32];
            float s = v0 + v1, s2 = v0 * v0 + v1 * v1;
            #pragma unroll
            for (int k = 16; k >= 1; k >>= 1) {
                s  += __shfl_xor_sync(0xffffffffu, s,  k);
                s2 += __shfl_xor_sync(0xffffffffu, s2, k);
            }
            float mu = s * (1.f / 64.f);
            float rstd = rsqrtf(s2 * (1.f / 64.f) - mu * mu + LN_EPS);
            ff_s[wj][lane]      = (v0 - mu) * rstd * ln_ff_w[lane]      + ln_ff_b[lane];
            ff_s[wj][lane + 32] = (v1 - mu) * rstd * ln_ff_w[lane + 32] + ln_ff_b[lane + 32];
        }
    }
    for (int i = t; i < 2048; i += 512) {
        float4 v = ((const float4*)W1)[i];
        int r = i >> 4, c = (i & 15) << 2;
        float* p = &Wsm[r * 65 + c];
        p[0] = v.x; p[1] = v.y; p[2] = v.z; p[3] = v.w;
    }
    __syncthreads();

    #pragma unroll
    for (int kk = 0; kk < 2; kk++) {
        int o = t + kk * 512, j = o >> 7, ee = o & 127;
        float acc = b1[ee];
        const float* w1r = &Wsm[ee * 65];
        #pragma unroll 16
        for (int dd = 0; dd < 64; dd++) acc += w1r[dd] * ff_s[j][dd];
        h1_s[j][ee] = fmaxf(acc, 0.f);
    }
    __syncthreads();

    for (int i = t; i < 2048; i += 512) {
        float4 v = ((const float4*)W2)[i];
        int r = i >> 5, c = (i & 31) << 2;
        float* p = &Wsm[r * 129 + c];
        p[0] = v.x; p[1] = v.y; p[2] = v.z; p[3] = v.w;
    }
    __syncthreads();

    {
        int j = t >> 6, dd = t & 63;
        float acc = b2[dd];
        const float* w2r = &Wsm[dd * 129];
        #pragma unroll 16
        for (int e = 0; e < 128; e++) acc += w2r[e] * h1_s[j][e];
        float val = sn_s[j][dd] + acc;
        sl_s[j][dd] = val;
        g_slots[b][j][dd] = val;
        if (last) out[(size_t)b * 512 + t] = val;
    }
    __syncthreads();

    if (!last)
        dev_prep(b, t, sl_s, Wsm, ff_s, Y_s, red, Wq, bq, Wk, bk,
                 ln_s_w, ln_s_b, ln_in_w, ln_in_b);
}

extern "C" void kernel_launch(void* const* d_in, const int* in_sizes, int n_in,
                              void* d_out, int out_size)
{
    const float* inputs = (const float*)d_in[0];
    const int*   mask   = (const int*)  d_in[1];
    const float* noise  = (const float*)d_in[2];
    const float* smu    = (const float*)d_in[3];
    const float* ssig   = (const float*)d_in[4];
    const float* Wq = (const float*)d_in[5];  const float* bq = (const float*)d_in[6];
    const float* Wk = (const float*)d_in[7];  const float* bk = (const float*)d_in[8];
    const float* Wv = (const float*)d_in[9];  const float* bv = (const float*)d_in[10];
    const float* W_ih = (const float*)d_in[11]; const float* b_ih = (const float*)d_in[12];
    const float* W_hh = (const float*)d_in[13]; const float* b_hh = (const float*)d_in[14];
    const float* W1 = (const float*)d_in[15]; const float* b1 = (const float*)d_in[16];
    const float* W2 = (const float*)d_in[17]; const float* b2 = (const float*)d_in[18];
    const float* ln_in_w = (const float*)d_in[19]; const float* ln_in_b = (const float*)d_in[20];
    const float* ln_s_w  = (const float*)d_in[21]; const float* ln_s_b  = (const float*)d_in[22];
    const float* ln_ff_w = (const float*)d_in[23]; const float* ln_ff_b = (const float*)d_in[24];
    float* out = (float*)d_out;

    static int smem_set = 0;
    if (!smem_set) {
        cudaFuncSetAttribute(k_upd_prep, cudaFuncAttributeMaxDynamicSharedMemorySize,
                             192 * 65 * (int)sizeof(float));
        cudaFuncSetAttribute(k_init_prep, cudaFuncAttributeMaxDynamicSharedMemorySize,
                             64 * 65 * (int)sizeof(float));
        smem_set = 1;
    }
    const int dynU = 192 * 65 * (int)sizeof(float);
    const int dynI = 64 * 65 * (int)sizeof(float);

    k_init_prep<<<BATCH, 512, dynI>>>(noise, smu, ssig, Wq, bq, Wk, bk,
                                      ln_s_w, ln_s_b, ln_in_w, ln_in_b);
    for (int it = 0; it < 3; it++) {
        k_stream<<<dim3(16, BATCH), 128>>>(inputs, mask);
        k_upd_prep<<<BATCH, 512, dynU>>>(Wv, bv, W_ih, b_ih, W_hh, b_hh, W1, b1, W2, b2,
                                         ln_in_w, ln_in_b, ln_ff_w, ln_ff_b,
                                         Wq, bq, Wk, bk, ln_s_w, ln_s_b,
                                         out, it == 2);
    }
}

// round 13
// speedup vs baseline: 4.3581x; 1.1743x over previous
#include <cuda_runtime.h>
#include <math.h>

#define BATCH 64
#define NTOK  4096
#define NS    8
#define SCALE 0.125f
#define EPSV  1e-8f
#define LN_EPS 1e-5f

typedef unsigned long long ull;

__device__ __forceinline__ ull pk2(float x, float y) {
    ull r; asm("mov.b64 %0, {%1, %2};" : "=l"(r) : "f"(x), "f"(y)); return r;
}
__device__ __forceinline__ float2 upk2(ull u) {
    float2 f; asm("mov.b64 {%0, %1}, %2;" : "=f"(f.x), "=f"(f.y) : "l"(u)); return f;
}
#define FMA2(d, a, b) asm("fma.rn.f32x2 %0, %1, %2, %0;" : "+l"(d) : "l"(a), "l"(b))
#define ADD2(d, a)    asm("add.rn.f32x2 %0, %1, %0;" : "+l"(d) : "l"(a))

__device__ float g_slots[BATCH][NS][64];
__device__ float g_Qk[BATCH][NS][64];
__device__ float g_T[BATCH][NS];
__device__ float g_C[BATCH][NS];
__device__ float g_Z[BATCH][NS][64];
__device__ float g_beta[BATCH][NS];
__device__ float g_Sa[BATCH][NS];

// ---- shared prep logic (512 threads, Wsm >= 64*65 floats, red = 24 floats) ----
__device__ __forceinline__ void dev_prep(
    int b, int t, const float (*sl)[64], float* Wsm,
    float (*sn)[64], float (*q)[64], float* red,
    const float* __restrict__ Wq, const float* __restrict__ bq,
    const float* __restrict__ Wk, const float* __restrict__ bk,
    const float* __restrict__ ln_s_w, const float* __restrict__ ln_s_b,
    const float* __restrict__ ln_in_w, const float* __restrict__ ln_in_b)
{
    float* bkq = red; float* ts = red + 8; float* cs = red + 16;
    if (t < 8) { bkq[t] = 0.f; ts[t] = 0.f; cs[t] = 0.f; }
    int w = t >> 5, lane = t & 31;
    if (w < 8) {
        float v0 = sl[w][lane], v1 = sl[w][lane + 32];
        float s = v0 + v1, s2 = v0 * v0 + v1 * v1;
        #pragma unroll
        for (int k = 16; k >= 1; k >>= 1) {
            s  += __shfl_xor_sync(0xffffffffu, s,  k);
            s2 += __shfl_xor_sync(0xffffffffu, s2, k);
        }
        float mu = s * (1.f / 64.f);
        float rstd = rsqrtf(s2 * (1.f / 64.f) - mu * mu + LN_EPS);
        sn[w][lane]      = (v0 - mu) * rstd * ln_s_w[lane]      + ln_s_b[lane];
        sn[w][lane + 32] = (v1 - mu) * rstd * ln_s_w[lane + 32] + ln_s_b[lane + 32];
    }
    for (int i = t; i < 1024; i += 512) {
        float4 v = ((const float4*)Wq)[i];
        int r = i >> 4, c = (i & 15) << 2;
        float* p = &Wsm[r * 65 + c];
        p[0] = v.x; p[1] = v.y; p[2] = v.z; p[3] = v.w;
    }
    __syncthreads();
    {
        int j = t >> 6, a = t & 63;
        float acc = bq[a];
        const float* wr = &Wsm[a * 65];
        #pragma unroll 16
        for (int c = 0; c < 64; c++) acc += sn[j][c] * wr[c];
        q[j][a] = acc;
        atomicAdd(&bkq[j], bk[a] * acc);
    }
    __syncthreads();
    for (int i = t; i < 1024; i += 512) {
        float4 v = ((const float4*)Wk)[i];
        int r = i >> 4, c = (i & 15) << 2;
        float* p = &Wsm[r * 65 + c];
        p[0] = v.x; p[1] = v.y; p[2] = v.z; p[3] = v.w;
    }
    __syncthreads();
    {
        int j = t >> 6, c = t & 63;
        float acc = 0.f;
        #pragma unroll 16
        for (int a = 0; a < 64; a++) acc += Wsm[a * 65 + c] * q[j][a];
        float Qkv = SCALE * ln_in_w[c] * acc;
        g_Qk[b][j][c] = Qkv;
        atomicAdd(&ts[j], Qkv);
        atomicAdd(&cs[j], SCALE * ln_in_b[c] * acc);
    }
    ((float*)g_Z[b])[t] = 0.f;
    __syncthreads();
    if (t < 8) {
        g_T[b][t] = ts[t];
        g_C[b][t] = cs[t] + SCALE * bkq[t];
        g_beta[b][t] = 0.f;
        g_Sa[b][t]   = 0.f;
    }
}

__global__ void __launch_bounds__(512) k_init_prep(
    const float* __restrict__ noise, const float* __restrict__ smu,
    const float* __restrict__ ssig,
    const float* __restrict__ Wq, const float* __restrict__ bq,
    const float* __restrict__ Wk, const float* __restrict__ bk,
    const float* __restrict__ ln_s_w, const float* __restrict__ ln_s_b,
    const float* __restrict__ ln_in_w, const float* __restrict__ ln_in_b)
{
    __shared__ float sl[NS][64], sn[NS][64], q[NS][64], red[24];
    extern __shared__ float Wsm[];
    int b = blockIdx.x, t = threadIdx.x;
    int c = t & 63;
    float v = smu[c] + ssig[c] * noise[b * 512 + t];
    sl[t >> 6][c] = v;
    ((float*)g_slots[b])[t] = v;
    __syncthreads();
    dev_prep(b, t, sl, Wsm, sn, q, red, Wq, bq, Wk, bk, ln_s_w, ln_s_b, ln_in_w, ln_in_b);
}

// ---- heavy pass: grid(8, BATCH), 128 threads, 256-row tiles, 2 rows/thread ----
#define XST 68
#define TROWS 256
__global__ void __launch_bounds__(128) k_stream(
    const float* __restrict__ inputs, const int* __restrict__ mask)
{
    __shared__ __align__(16) ulonglong2 Qk2[NS][16];
    __shared__ float T_s[NS], C_s[NS];
    extern __shared__ __align__(16) unsigned char dynsm[];
    float* x_s = (float*)dynsm;                              // TROWS * XST floats
    ull (*alphaT2)[TROWS] = (ull(*)[TROWS])(dynsm + TROWS * XST * 4);

    int b = blockIdx.y, chunk = blockIdx.x, t = threadIdx.x;
    int w = t >> 5, lane = t & 31;

    {
        const float4* qg = (const float4*)&g_Qk[b][0][0];
        ((float4*)Qk2)[t] = qg[t];
        if (t < 8) { T_s[t] = g_T[b][t]; C_s[t] = g_C[b][t]; }
    }
    __syncthreads();

    float sa_acc[8], be_acc[8];
    ull zp[8];
    #pragma unroll
    for (int j = 0; j < 8; j++) { sa_acc[j] = 0.f; be_acc[j] = 0.f; zp[j] = 0ull; }

    unsigned int xbase = (unsigned int)__cvta_generic_to_shared(x_s);

    #pragma unroll 1
    for (int tile = 0; tile < 2; tile++) {
        int base = chunk * 512 + tile * 256;
        float mval0 = (mask[(size_t)b * NTOK + base + t]       != 0) ? 1.f : 0.f;
        float mval1 = (mask[(size_t)b * NTOK + base + t + 128] != 0) ? 1.f : 0.f;

        // async coalesced tile copy: 256 rows x 64 floats -> x_s (row stride XST)
        {
            const float4* gsrc = (const float4*)(inputs + ((size_t)b * NTOK + base) * 64);
            #pragma unroll
            for (int i = 0; i < 32; i++) {
                int idx = i * 128 + t;
                int r = idx >> 4, ic = idx & 15;
                unsigned int dst = xbase + (unsigned int)((r * (XST / 4) + ic) * 16);
                asm volatile("cp.async.ca.shared.global [%0], [%1], 16;"
                             :: "r"(dst), "l"(gsrc + idx));
            }
            asm volatile("cp.async.commit_group;");
            asm volatile("cp.async.wait_group 0;");
        }
        __syncthreads();

        // ---- phase A: thread t = rows t and t+128; Qk load shared by both rows ----
        {
            const ulonglong2* xr0 = (const ulonglong2*)&x_s[t * XST];
            const ulonglong2* xr1 = (const ulonglong2*)&x_s[(t + 128) * XST];
            ull dacc0[8], dacc1[8], sac0 = 0ull, s2c0 = 0ull, sac1 = 0ull, s2c1 = 0ull;
            #pragma unroll
            for (int j = 0; j < 8; j++) { dacc0[j] = 0ull; dacc1[j] = 0ull; }
            #pragma unroll
            for (int i = 0; i < 16; i++) {
                ulonglong2 xv0 = xr0[i];
                ulonglong2 xv1 = xr1[i];
                ADD2(sac0, xv0.x); ADD2(sac0, xv0.y);
                FMA2(s2c0, xv0.x, xv0.x); FMA2(s2c0, xv0.y, xv0.y);
                ADD2(sac1, xv1.x); ADD2(sac1, xv1.y);
                FMA2(s2c1, xv1.x, xv1.x); FMA2(s2c1, xv1.y, xv1.y);
                #pragma unroll
                for (int j = 0; j < 8; j++) {
                    ulonglong2 qk = Qk2[j][i];
                    FMA2(dacc0[j], xv0.x, qk.x);
                    FMA2(dacc0[j], xv0.y, qk.y);
                    FMA2(dacc1[j], xv1.x, qk.x);
                    FMA2(dacc1[j], xv1.y, qk.y);
                }
            }
            #pragma unroll
            for (int r = 0; r < 2; r++) {
                ull sacc  = r ? sac1 : sac0;
                ull s2acc = r ? s2c1 : s2c0;
                float mval = r ? mval1 : mval0;
                int rowt = t + r * 128;
                float2 sf = upk2(sacc), s2f = upk2(s2acc);
                float s = sf.x + sf.y, s2 = s2f.x + s2f.y;
                float mu = s * (1.f / 64.f);
                float rstd = rsqrtf(s2 * (1.f / 64.f) - mu * mu + LN_EPS);
                float d[8];
                #pragma unroll
                for (int j = 0; j < 8; j++) {
                    float2 dd = upk2(r ? dacc1[j] : dacc0[j]);
                    d[j] = rstd * ((dd.x + dd.y) - mu * T_s[j]) + C_s[j];
                }
                float mx = d[0];
                #pragma unroll
                for (int j = 1; j < 8; j++) mx = fmaxf(mx, d[j]);
                float e[8], se = 0.f;
                #pragma unroll
                for (int j = 0; j < 8; j++) { e[j] = __expf(d[j] - mx); se += e[j]; }
                float inv = __fdividef(1.f, se) * mval;
                float epsm = EPSV * mval;
                #pragma unroll
                for (int j = 0; j < 8; j++) {
                    float a  = e[j] * inv + epsm;
                    float al = a * rstd;
                    sa_acc[j] += a;
                    be_acc[j] += al * mu;
                    alphaT2[j][rowt] = pk2(al, al);
                }
            }
        }
        __syncthreads();

        // ---- phase B: warp w -> rows [64w, 64w+64); lane -> channels (2lane,2lane+1)
        for (int r0 = w * 64; r0 < w * 64 + 64; r0 += 4) {
            ull x0 = *(const ull*)&x_s[(r0 + 0) * XST + 2 * lane];
            ull x1 = *(const ull*)&x_s[(r0 + 1) * XST + 2 * lane];
            ull x2 = *(const ull*)&x_s[(r0 + 2) * XST + 2 * lane];
            ull x3 = *(const ull*)&x_s[(r0 + 3) * XST + 2 * lane];
            #pragma unroll
            for (int j = 0; j < 8; j++) {
                ulonglong2 aa = *(const ulonglong2*)&alphaT2[j][r0];
                ulonglong2 ab = *(const ulonglong2*)&alphaT2[j][r0 + 2];
                FMA2(zp[j], aa.x, x0);
                FMA2(zp[j], aa.y, x1);
                FMA2(zp[j], ab.x, x2);
                FMA2(zp[j], ab.y, x3);
            }
        }
        __syncthreads();
    }

    // ---- merge ----
    #pragma unroll
    for (int j = 0; j < 8; j++) {
        float2 zz = upk2(zp[j]);
        atomicAdd(&g_Z[b][j][2 * lane],     zz.x);
        atomicAdd(&g_Z[b][j][2 * lane + 1], zz.y);
    }
    #pragma unroll
    for (int j = 0; j < 8; j++) {
        float sv = sa_acc[j], bv2 = be_acc[j];
        #pragma unroll
        for (int k = 16; k >= 1; k >>= 1) {
            sv  += __shfl_xor_sync(0xffffffffu, sv,  k);
            bv2 += __shfl_xor_sync(0xffffffffu, bv2, k);
        }
        if (lane == 0) {
            atomicAdd(&g_Sa[b][j],   sv);
            atomicAdd(&g_beta[b][j], bv2);
        }
    }
}

// ---- update (GRU + MLP) + next prep; ALL weights staged up-front in one shot ----
// smem float offsets
#define OFF_WV  0
#define OFF_WIH 4160
#define OFF_WHH 16640
#define OFF_W1  29120
#define OFF_W2  37440
#define WSM_TOT 45696
__global__ void __launch_bounds__(512) k_upd_prep(
    const float* __restrict__ Wv,  const float* __restrict__ bv,
    const float* __restrict__ W_ih, const float* __restrict__ b_ih,
    const float* __restrict__ W_hh, const float* __restrict__ b_hh,
    const float* __restrict__ W1,  const float* __restrict__ b1,
    const float* __restrict__ W2,  const float* __restrict__ b2,
    const float* __restrict__ ln_in_w, const float* __restrict__ ln_in_b,
    const float* __restrict__ ln_ff_w, const float* __restrict__ ln_ff_b,
    const float* __restrict__ Wq, const float* __restrict__ bq,
    const float* __restrict__ Wk, const float* __restrict__ bk,
    const float* __restrict__ ln_s_w, const float* __restrict__ ln_s_b,
    float* __restrict__ out, int last)
{
    extern __shared__ float Wsm[];          // WSM_TOT floats = 182784 B
    __shared__ float Y_s[NS][64];
    __shared__ float sl_s[NS][64];
    __shared__ float upd_s[NS][64];
    __shared__ float gx_s[NS][192];
    __shared__ float gh_s[NS][192];
    __shared__ float sn_s[NS][64];
    __shared__ float ff_s[NS][64];
    __shared__ float h1_s[NS][128];
    __shared__ float Sa_s[NS], Be_s[NS];
    __shared__ float red[24];

    int b = blockIdx.x, t = threadIdx.x;
    if (t < 8) { Sa_s[t] = g_Sa[b][t]; Be_s[t] = g_beta[b][t]; }
    ((float*)sl_s)[t] = ((const float*)g_slots[b])[t];

    // ---- stage ALL weights at once: every LDG in flight together ----
    for (int i = t; i < 1024; i += 512) {            // Wv [64][64]
        float4 v = ((const float4*)Wv)[i];
        float* p = &Wsm[OFF_WV + (i >> 4) * 65 + ((i & 15) << 2)];
        p[0] = v.x; p[1] = v.y; p[2] = v.z; p[3] = v.w;
    }
    for (int i = t; i < 3072; i += 512) {            // W_ih [192][64]
        float4 v = ((const float4*)W_ih)[i];
        float* p = &Wsm[OFF_WIH + (i >> 4) * 65 + ((i & 15) << 2)];
        p[0] = v.x; p[1] = v.y; p[2] = v.z; p[3] = v.w;
    }
    for (int i = t; i < 3072; i += 512) {            // W_hh [192][64]
        float4 v = ((const float4*)W_hh)[i];
        float* p = &Wsm[OFF_WHH + (i >> 4) * 65 + ((i & 15) << 2)];
        p[0] = v.x; p[1] = v.y; p[2] = v.z; p[3] = v.w;
    }
    for (int i = t; i < 2048; i += 512) {            // W1 [128][64]
        float4 v = ((const float4*)W1)[i];
        float* p = &Wsm[OFF_W1 + (i >> 4) * 65 + ((i & 15) << 2)];
        p[0] = v.x; p[1] = v.y; p[2] = v.z; p[3] = v.w;
    }
    for (int i = t; i < 2048; i += 512) {            // W2 [64][128] -> stride 129
        float4 v = ((const float4*)W2)[i];
        float* p = &Wsm[OFF_W2 + (i >> 5) * 129 + ((i & 31) << 2)];
        p[0] = v.x; p[1] = v.y; p[2] = v.z; p[3] = v.w;
    }
    __syncthreads();

    {
        int j = t >> 6, c = t & 63;
        Y_s[j][c] = ln_in_w[c] * (g_Z[b][j][c] - Be_s[j]) + ln_in_b[c] * Sa_s[j];
    }
    __syncthreads();

    {
        int j = t >> 6, dv = t & 63;
        float acc = 0.f;
        const float* wr = &Wsm[OFF_WV + dv * 65];
        #pragma unroll 16
        for (int c = 0; c < 64; c++) acc += wr[c] * Y_s[j][c];
        upd_s[j][dv] = acc * __fdividef(1.f, Sa_s[j]) + bv[dv];
    }
    __syncthreads();

    #pragma unroll
    for (int kk = 0; kk < 3; kk++) {
        int o = t + kk * 512, j = o / 192, g = o % 192;
        float ax = b_ih[g], ah = b_hh[g];
        const float* wx = &Wsm[OFF_WIH + g * 65];
        const float* wh = &Wsm[OFF_WHH + g * 65];
        #pragma unroll 16
        for (int dd = 0; dd < 64; dd++) {
            ax += wx[dd] * upd_s[j][dd];
            ah += wh[dd] * sl_s[j][dd];
        }
        gx_s[j][g] = ax; gh_s[j][g] = ah;
    }
    __syncthreads();

    {
        int j = t >> 6, dd = t & 63;
        float r = 1.f / (1.f + __expf(-(gx_s[j][dd] + gh_s[j][dd])));
        float z = 1.f / (1.f + __expf(-(gx_s[j][64 + dd] + gh_s[j][64 + dd])));
        float nn = tanhf(gx_s[j][128 + dd] + r * gh_s[j][128 + dd]);
        sn_s[j][dd] = (1.f - z) * nn + z * sl_s[j][dd];
    }
    __syncthreads();

    {
        int wj = t >> 5, lane = t & 31;
        if (wj < 8) {
            float v0 = sn_s[wj][lane], v1 = sn_s[wj][lane + 32];
            float s = v0 + v1, s2 = v0 * v0 + v1 * v1;
            #pragma unroll
            for (int k = 16; k >= 1; k >>= 1) {
                s  += __shfl_xor_sync(0xffffffffu, s,  k);
                s2 += __shfl_xor_sync(0xffffffffu, s2, k);
            }
            float mu = s * (1.f / 64.f);
            float rstd = rsqrtf(s2 * (1.f / 64.f) - mu * mu + LN_EPS);
            ff_s[wj][lane]      = (v0 - mu) * rstd * ln_ff_w[lane]      + ln_ff_b[lane];
            ff_s[wj][lane + 32] = (v1 - mu) * rstd * ln_ff_w[lane + 32] + ln_ff_b[lane + 32];
        }
    }
    __syncthreads();

    #pragma unroll
    for (int kk = 0; kk < 2; kk++) {
        int o = t + kk * 512, j = o >> 7, ee = o & 127;
        float acc = b1[ee];
        const float* w1r = &Wsm[OFF_W1 + ee * 65];
        #pragma unroll 16
        for (int dd = 0; dd < 64; dd++) acc += w1r[dd] * ff_s[j][dd];
        h1_s[j][ee] = fmaxf(acc, 0.f);
    }
    __syncthreads();

    {
        int j = t >> 6, dd = t & 63;
        float acc = b2[dd];
        const float* w2r = &Wsm[OFF_W2 + dd * 129];
        #pragma unroll 16
        for (int e = 0; e < 128; e++) acc += w2r[e] * h1_s[j][e];
        float val = sn_s[j][dd] + acc;
        sl_s[j][dd] = val;
        g_slots[b][j][dd] = val;
        if (last) out[(size_t)b * 512 + t] = val;
    }
    __syncthreads();

    if (!last)
        dev_prep(b, t, sl_s, Wsm, ff_s, Y_s, red, Wq, bq, Wk, bk,
                 ln_s_w, ln_s_b, ln_in_w, ln_in_b);
}

extern "C" void kernel_launch(void* const* d_in, const int* in_sizes, int n_in,
                              void* d_out, int out_size)
{
    const float* inputs = (const float*)d_in[0];
    const int*   mask   = (const int*)  d_in[1];
    const float* noise  = (const float*)d_in[2];
    const float* smu    = (const float*)d_in[3];
    const float* ssig   = (const float*)d_in[4];
    const float* Wq = (const float*)d_in[5];  const float* bq = (const float*)d_in[6];
    const float* Wk = (const float*)d_in[7];  const float* bk = (const float*)d_in[8];
    const float* Wv = (const float*)d_in[9];  const float* bv = (const float*)d_in[10];
    const float* W_ih = (const float*)d_in[11]; const float* b_ih = (const float*)d_in[12];
    const float* W_hh = (const float*)d_in[13]; const float* b_hh = (const float*)d_in[14];
    const float* W1 = (const float*)d_in[15]; const float* b1 = (const float*)d_in[16];
    const float* W2 = (const float*)d_in[17]; const float* b2 = (const float*)d_in[18];
    const float* ln_in_w = (const float*)d_in[19]; const float* ln_in_b = (const float*)d_in[20];
    const float* ln_s_w  = (const float*)d_in[21]; const float* ln_s_b  = (const float*)d_in[22];
    const float* ln_ff_w = (const float*)d_in[23]; const float* ln_ff_b = (const float*)d_in[24];
    float* out = (float*)d_out;

    const int dynU = WSM_TOT * (int)sizeof(float);                 // 182784
    const int dynI = 64 * 65 * (int)sizeof(float);                 // 16640
    const int dynS = (TROWS * XST + NS * TROWS * 2) * (int)sizeof(float); // 86016

    static int smem_set = 0;
    if (!smem_set) {
        cudaFuncSetAttribute(k_upd_prep, cudaFuncAttributeMaxDynamicSharedMemorySize, dynU);
        cudaFuncSetAttribute(k_init_prep, cudaFuncAttributeMaxDynamicSharedMemorySize, dynI);
        cudaFuncSetAttribute(k_stream, cudaFuncAttributeMaxDynamicSharedMemorySize, dynS);
        smem_set = 1;
    }

    k_init_prep<<<BATCH, 512, dynI>>>(noise, smu, ssig, Wq, bq, Wk, bk,
                                      ln_s_w, ln_s_b, ln_in_w, ln_in_b);
    for (int it = 0; it < 3; it++) {
        k_stream<<<dim3(8, BATCH), 128, dynS>>>(inputs, mask);
        k_upd_prep<<<BATCH, 512, dynU>>>(Wv, bv, W_ih, b_ih, W_hh, b_hh, W1, b1, W2, b2,
                                         ln_in_w, ln_in_b, ln_ff_w, ln_ff_b,
                                         Wq, bq, Wk, bk, ln_s_w, ln_s_b,
                                         out, it == 2);
    }
}